// round 15
// baseline (speedup 1.0000x reference)
#include <cuda_runtime.h>
#include <cstdint>

#define CN0  400000
#define CN1  40000
#define CN2  4000
#define CIN  128
#define CHID 256
#define COUT 64
#define CE1  640000
#define CE2  64000
#define NB1  40
#define NB2  4
#define NBT  (NB1 + NB2)
#define MSPLIT 20480          /* chunk0 rows (320*64); chunk1 = 19520 (305*64) */

// ---- scratch (device globals: zero-initialized at load; the graph is
//      self-cleaning: scan re-zeroes cnt, fill re-zeroes scan_done) ----
__device__ float g_agg1[CN1 * CIN];
__device__ float g_h   [CN1 * CHID];
__device__ int   g_cnt1[CN1];
__device__ int   g_off1[CN1 + 1];
__device__ int   g_csr1[CE1];
__device__ int   g_pos1[CE1];
__device__ int   g_cnt2[CN2];
__device__ int   g_off2[CN2 + 1];
__device__ int   g_csr2[CE2];
__device__ int   g_pos2[CE2];
__device__ int   g_bsum[64];
__device__ int   g_scan_done;

// ---------------------------------------------------------------------------
// merged histogram + ticket assignment (fill pass needs NO atomics)
// ---------------------------------------------------------------------------
__global__ void k_count(const int* __restrict__ d1, const int* __restrict__ d2,
                        int E1, int E2) {
    int i = blockIdx.x * blockDim.x + threadIdx.x;
    if (i < E1) {
        g_pos1[i] = atomicAdd(g_cnt1 + d1[i], 1);
    } else {
        int j = i - E1;
        if (j < E2) g_pos2[j] = atomicAdd(g_cnt2 + d2[j], 1);
    }
}

// ---------------------------------------------------------------------------
// Single-kernel segmented scan with device-wide spin barrier (44 blocks).
// Also re-zeroes cnt[] for the next graph replay.
// ---------------------------------------------------------------------------
__global__ void __launch_bounds__(1024) k_scan(int E1, int E2) {
    int b = blockIdx.x;
    int lay = (b >= NB1);
    int bb = lay ? b - NB1 : b;
    int n = lay ? CN2 : CN1;
    int segbase = lay ? NB1 : 0;
    int* cnt = lay ? g_cnt2 : g_cnt1;
    int* off = lay ? g_off2 : g_off1;
    __shared__ int ps[1024];
    __shared__ int add_s;
    int t = threadIdx.x;
    int i = bb * 1024 + t;
    int v = (i < n) ? cnt[i] : 0;
    ps[t] = v;
    __syncthreads();
    #pragma unroll
    for (int d = 1; d < 1024; d <<= 1) {
        int u = (t >= d) ? ps[t - d] : 0;
        __syncthreads();
        ps[t] += u;
        __syncthreads();
    }
    int local_ex = ps[t] - v;
    if (t == 0) g_bsum[b] = ps[1023];
    __threadfence();
    __syncthreads();
    if (t == 0) {
        atomicAdd(&g_scan_done, 1);
        while (*(volatile int*)&g_scan_done < NBT) { }
        __threadfence();
        int s = 0;
        for (int j = segbase; j < b; j++) s += g_bsum[j];
        add_s = s;
    }
    __syncthreads();
    int add = add_s;
    if (i < n) { off[i] = local_ex + add; cnt[i] = 0; }
    if (i == 0) off[n] = lay ? E2 : E1;
}

// atomic-free fill (ticket precomputed); also resets the scan barrier counter
__global__ void k_fill(const int* __restrict__ s1, const int* __restrict__ d1,
                       const int* __restrict__ s2, const int* __restrict__ d2,
                       int E1, int E2) {
    int i = blockIdx.x * blockDim.x + threadIdx.x;
    if (i == 0) g_scan_done = 0;
    if (i < E1) {
        int d = d1[i];
        g_csr1[g_off1[d] + g_pos1[i]] = s1[i];
    } else {
        int j = i - E1;
        if (j < E2) {
            int d = d2[j];
            g_csr2[g_off2[d] + g_pos2[j]] = s2[j];
        }
    }
}

// ---------------------------------------------------------------------------
// layer-1 gather-mean over row range [row0, row1): warp per dst row, unroll 8
// ---------------------------------------------------------------------------
__global__ void __launch_bounds__(256) k_gather1(const float* __restrict__ x,
                                                 int row0, int row1) {
    int w = row0 + ((blockIdx.x * blockDim.x + threadIdx.x) >> 5);
    if (w >= row1) return;
    int lane = threadIdx.x & 31;
    int e0 = g_off1[w], e1 = g_off1[w + 1];
    float4 acc = make_float4(0.f, 0.f, 0.f, 0.f);
    int i = e0;
    for (; i + 7 < e1; i += 8) {
        int sid[8];
        #pragma unroll
        for (int j = 0; j < 8; j++) sid[j] = g_csr1[i + j];
        float4 v[8];
        #pragma unroll
        for (int j = 0; j < 8; j++)
            v[j] = ((const float4*)(x + (size_t)sid[j] * CIN))[lane];
        #pragma unroll
        for (int j = 0; j < 8; j++) {
            acc.x += v[j].x; acc.y += v[j].y; acc.z += v[j].z; acc.w += v[j].w;
        }
    }
    for (; i + 3 < e1; i += 4) {
        int s0 = g_csr1[i], s1 = g_csr1[i + 1], s2 = g_csr1[i + 2], s3 = g_csr1[i + 3];
        float4 v0 = ((const float4*)(x + (size_t)s0 * CIN))[lane];
        float4 v1 = ((const float4*)(x + (size_t)s1 * CIN))[lane];
        float4 v2 = ((const float4*)(x + (size_t)s2 * CIN))[lane];
        float4 v3 = ((const float4*)(x + (size_t)s3 * CIN))[lane];
        acc.x += v0.x + v1.x + v2.x + v3.x;
        acc.y += v0.y + v1.y + v2.y + v3.y;
        acc.z += v0.z + v1.z + v2.z + v3.z;
        acc.w += v0.w + v1.w + v2.w + v3.w;
    }
    for (; i < e1; i++) {
        int s = g_csr1[i];
        float4 v = ((const float4*)(x + (size_t)s * CIN))[lane];
        acc.x += v.x; acc.y += v.y; acc.z += v.z; acc.w += v.w;
    }
    float id = 1.0f / fmaxf((float)(e1 - e0), 1.0f);
    acc.x *= id; acc.y *= id; acc.z *= id; acc.w *= id;
    ((float4*)(g_agg1 + (size_t)w * CIN))[lane] = acc;
}

// ---------------------------------------------------------------------------
// tf32 helpers — raw fp32 bits fed to mma.tf32 (HW truncates)
// ---------------------------------------------------------------------------
__device__ __forceinline__ void mma_tf32(float* c, const uint32_t* a, const uint32_t* b) {
    asm volatile(
        "mma.sync.aligned.m16n8k8.row.col.f32.tf32.tf32.f32 "
        "{%0,%1,%2,%3}, {%4,%5,%6,%7}, {%8,%9}, {%0,%1,%2,%3};"
        : "+f"(c[0]), "+f"(c[1]), "+f"(c[2]), "+f"(c[3])
        : "r"(a[0]), "r"(a[1]), "r"(a[2]), "r"(a[3]), "r"(b[0]), "r"(b[1]));
}

__device__ __forceinline__ uint32_t s2u(const void* p) {
    return (uint32_t)__cvta_generic_to_shared(p);
}

__device__ __forceinline__ void cp16(uint32_t dst, const void* src) {
    asm volatile("cp.async.cg.shared.global [%0], [%1], 16;"
                 :: "r"(dst), "l"(src));
}

// ---------------------------------------------------------------------------
// layer-1 GEMM (tf32, 3-stage cp.async pipeline, BM=64 x BN=256), row base m0b
// ---------------------------------------------------------------------------
#define A_ST 1280
#define B_ST 4224
#define SMEM_GEMM1 ((3 * (A_ST + B_ST)) * 4)

__global__ void __launch_bounds__(256, 2) k_gemm1(const float* __restrict__ x,
                                                  const float* __restrict__ wl,
                                                  const float* __restrict__ wr,
                                                  const float* __restrict__ bias,
                                                  int m0b) {
    extern __shared__ float sm[];
    float* Abuf = sm;
    float* Bbuf = sm + 3 * A_ST;

    const int t = threadIdx.x;
    const int lane = t & 31, warp = t >> 5;
    const int warp_m = warp & 1;
    const int warp_n = warp >> 1;
    const int m0 = m0b + blockIdx.x * 64;
    const int fr = lane >> 2;
    const int fc = lane & 3;

    const int a_row = t >> 2,  a_kq = (t & 3) * 4;
    const int b_nq  = (t & 63) * 4;

    float acc[2][8][4] = {};

    auto issue = [&](int it, int st) {
        const int kk = (it & 7) * 16;
        const float* Abase = (it < 8) ? g_agg1 : x;
        const float* Bbase = (it < 8) ? wl : wr;
        float* As = Abuf + st * A_ST;
        float* Bs = Bbuf + st * B_ST;
        cp16(s2u(As + a_row * 20 + a_kq),
             Abase + (size_t)(m0 + a_row) * CIN + kk + a_kq);
        #pragma unroll
        for (int i = 0; i < 4; i++) {
            int krow = (t + i * 256) >> 6;
            cp16(s2u(Bs + krow * 264 + b_nq),
                 Bbase + (size_t)(kk + krow) * CHID + b_nq);
        }
    };

    issue(0, 0);
    asm volatile("cp.async.commit_group;");
    issue(1, 1);
    asm volatile("cp.async.commit_group;");

    int st = 0;
    for (int it = 0; it < 16; ++it) {
        asm volatile("cp.async.wait_group 1;");
        __syncthreads();
        if (it + 2 < 16) issue(it + 2, (st + 2) % 3);
        asm volatile("cp.async.commit_group;");

        const uint32_t* A = (const uint32_t*)(Abuf + st * A_ST);
        const uint32_t* B = (const uint32_t*)(Bbuf + st * B_ST);
        #pragma unroll
        for (int ks = 0; ks < 2; ks++) {
            const int kb = ks * 8;
            uint32_t a[2][4], b[8][2];
            #pragma unroll
            for (int mt = 0; mt < 2; mt++) {
                int mr = warp_m * 32 + mt * 16 + fr;
                a[mt][0] = A[mr * 20 + kb + fc];
                a[mt][1] = A[(mr + 8) * 20 + kb + fc];
                a[mt][2] = A[mr * 20 + kb + fc + 4];
                a[mt][3] = A[(mr + 8) * 20 + kb + fc + 4];
            }
            #pragma unroll
            for (int nt = 0; nt < 8; nt++) {
                int nc = warp_n * 64 + nt * 8 + fr;
                b[nt][0] = B[(kb + fc) * 264 + nc];
                b[nt][1] = B[(kb + fc + 4) * 264 + nc];
            }
            #pragma unroll
            for (int mt = 0; mt < 2; mt++)
                #pragma unroll
                for (int nt = 0; nt < 8; nt++)
                    mma_tf32(acc[mt][nt], a[mt], b[nt]);
        }
        st = (st + 1) % 3;
    }

    #pragma unroll
    for (int mt = 0; mt < 2; mt++) {
        int gm = m0 + warp_m * 32 + mt * 16 + fr;
        #pragma unroll
        for (int nt = 0; nt < 8; nt++) {
            int gn = warp_n * 64 + nt * 8 + (fc << 1);
            float b0 = bias[gn], b1 = bias[gn + 1];
            float2 v0 = make_float2(fmaxf(acc[mt][nt][0] + b0, 0.f),
                                    fmaxf(acc[mt][nt][1] + b1, 0.f));
            *(float2*)(g_h + (size_t)gm * CHID + gn) = v0;
            float2 v1 = make_float2(fmaxf(acc[mt][nt][2] + b0, 0.f),
                                    fmaxf(acc[mt][nt][3] + b1, 0.f));
            *(float2*)(g_h + (size_t)(gm + 8) * CHID + gn) = v1;
        }
    }
}

// ---------------------------------------------------------------------------
// FUSED layer-2: gather-mean + GEMM + log_softmax. Warp per dst row.
// Lane owns cols {2*lane, 2*lane+1}: float2 weight/bias/output accesses.
// ---------------------------------------------------------------------------
__global__ void __launch_bounds__(256) k_gemm2(const float* __restrict__ wl,
                                               const float* __restrict__ wr,
                                               const float* __restrict__ bias,
                                               float* __restrict__ out) {
    __shared__ float As[8][512];
    int warp = threadIdx.x >> 5, lane = threadIdx.x & 31;
    int m = blockIdx.x * 8 + warp;
    if (m >= CN2) return;

    {
        int e0 = g_off2[m], e1 = g_off2[m + 1];
        float4 a0 = make_float4(0.f, 0.f, 0.f, 0.f);
        float4 a1 = a0;
        int i = e0;
        for (; i + 1 < e1; i += 2) {
            const float4* p0 = (const float4*)(g_h + (size_t)g_csr2[i] * CHID);
            const float4* p1 = (const float4*)(g_h + (size_t)g_csr2[i + 1] * CHID);
            float4 u0 = p0[lane], u1 = p0[lane + 32];
            float4 v0 = p1[lane], v1 = p1[lane + 32];
            a0.x += u0.x + v0.x; a0.y += u0.y + v0.y;
            a0.z += u0.z + v0.z; a0.w += u0.w + v0.w;
            a1.x += u1.x + v1.x; a1.y += u1.y + v1.y;
            a1.z += u1.z + v1.z; a1.w += u1.w + v1.w;
        }
        for (; i < e1; i++) {
            const float4* p = (const float4*)(g_h + (size_t)g_csr2[i] * CHID);
            float4 u0 = p[lane], u1 = p[lane + 32];
            a0.x += u0.x; a0.y += u0.y; a0.z += u0.z; a0.w += u0.w;
            a1.x += u1.x; a1.y += u1.y; a1.z += u1.z; a1.w += u1.w;
        }
        float id = 1.0f / fmaxf((float)(e1 - e0), 1.0f);
        a0.x *= id; a0.y *= id; a0.z *= id; a0.w *= id;
        a1.x *= id; a1.y *= id; a1.z *= id; a1.w *= id;
        ((float4*)As[warp])[lane] = a0;
        ((float4*)As[warp])[lane + 32] = a1;
    }
    #pragma unroll
    for (int i = 0; i < 8; i++)
        As[warp][CHID + lane + 32 * i] = g_h[(size_t)m * CHID + lane + 32 * i];
    __syncwarp();

    const float2* wlv = (const float2*)wl;
    const float2* wrv = (const float2*)wr;
    float acc0 = 0.f, acc1 = 0.f;
    const float* A = As[warp];
    #pragma unroll 8
    for (int k = 0; k < CHID; k++) {
        float a = A[k];
        float2 w = wlv[k * 32 + lane];
        acc0 += a * w.x;
        acc1 += a * w.y;
    }
    #pragma unroll 8
    for (int k = 0; k < CHID; k++) {
        float a = A[CHID + k];
        float2 w = wrv[k * 32 + lane];
        acc0 += a * w.x;
        acc1 += a * w.y;
    }
    float2 bv = ((const float2*)bias)[lane];
    acc0 += bv.x;
    acc1 += bv.y;

    float mx = fmaxf(acc0, acc1);
    #pragma unroll
    for (int o = 16; o > 0; o >>= 1) mx = fmaxf(mx, __shfl_xor_sync(0xFFFFFFFFu, mx, o));
    float s = expf(acc0 - mx) + expf(acc1 - mx);
    #pragma unroll
    for (int o = 16; o > 0; o >>= 1) s += __shfl_xor_sync(0xFFFFFFFFu, s, o);
    float lse = mx + logf(s);
    ((float2*)(out + (size_t)m * COUT))[lane] = make_float2(acc0 - lse, acc1 - lse);
}

// ---------------------------------------------------------------------------
extern "C" void kernel_launch(void* const* d_in, const int* in_sizes, int n_in,
                              void* d_out, int out_size) {
    const float* x    = (const float*)d_in[0];
    const int*   src1 = (const int*)d_in[1];
    const int*   dst1 = (const int*)d_in[2];
    const int*   src2 = (const int*)d_in[3];
    const int*   dst2 = (const int*)d_in[4];
    const float* wl1  = (const float*)d_in[5];
    const float* bl1  = (const float*)d_in[6];
    const float* wr1  = (const float*)d_in[7];
    const float* wl2  = (const float*)d_in[8];
    const float* bl2  = (const float*)d_in[9];
    const float* wr2  = (const float*)d_in[10];
    int E1 = in_sizes[1];
    int E2 = in_sizes[3];

    // one-time setup on the first (uncaptured) correctness call
    static cudaStream_t s_side = nullptr;
    static cudaEvent_t  e_g0 = nullptr, e_c1 = nullptr;
    static bool init_done = false;
    if (!init_done) {
        cudaStreamCreateWithFlags(&s_side, cudaStreamNonBlocking);
        cudaEventCreateWithFlags(&e_g0, cudaEventDisableTiming);
        cudaEventCreateWithFlags(&e_c1, cudaEventDisableTiming);
        cudaFuncSetAttribute(k_gemm1, cudaFuncAttributeMaxDynamicSharedMemorySize,
                             SMEM_GEMM1);
        init_done = true;
    }

    // CSR build (default stream)
    k_count<<<(E1 + E2 + 255) / 256, 256>>>(dst1, dst2, E1, E2);
    k_scan<<<NBT, 1024>>>(E1, E2);
    k_fill<<<(E1 + E2 + 255) / 256, 256>>>(src1, dst1, src2, dst2, E1, E2);

    // chunk 0: gather then gemm (default stream)
    k_gather1<<<MSPLIT * 32 / 256, 256>>>(x, 0, MSPLIT);
    cudaEventRecord(e_g0, 0);
    k_gemm1<<<MSPLIT / 64, 256, SMEM_GEMM1>>>(x, wl1, wr1, bl1, 0);

    // chunk 1 on side stream: starts when gather_c0 is done -> overlaps gemm_c0
    cudaStreamWaitEvent(s_side, e_g0, 0);
    k_gather1<<<((CN1 - MSPLIT) * 32 + 255) / 256, 256, 0, s_side>>>(x, MSPLIT, CN1);
    k_gemm1<<<(CN1 - MSPLIT) / 64, 256, SMEM_GEMM1, s_side>>>(x, wl1, wr1, bl1, MSPLIT);
    cudaEventRecord(e_c1, s_side);

    // join, then layer 2
    cudaStreamWaitEvent(0, e_c1, 0);
    k_gemm2<<<(CN2 + 7) / 8, 256>>>(wl2, wr2, bl2, (float*)d_out);
}

// round 17
// speedup vs baseline: 1.0502x; 1.0502x over previous
#include <cuda_runtime.h>
#include <cstdint>

#define CN0  400000
#define CN1  40000
#define CN2  4000
#define CIN  128
#define CHID 256
#define COUT 64
#define CE1  640000
#define CE2  64000
#define NB1  40
#define NB2  4
#define NBT  (NB1 + NB2)
#define NBG  148              /* persistent CSR kernel: 1 CTA per SM */

// ---- scratch (device globals: zero-initialized at load; graph self-cleans:
//      scan phase re-zeroes cnt, grid barriers self-reset in rotation) ----
__device__ float g_agg1[CN1 * CIN];
__device__ float g_h   [CN1 * CHID];
__device__ int   g_cnt1[CN1];
__device__ int   g_off1[CN1 + 1];
__device__ int   g_csr1[CE1];
__device__ int   g_pos1[CE1];
__device__ int   g_cnt2[CN2];
__device__ int   g_off2[CN2 + 1];
__device__ int   g_csr2[CE2];
__device__ int   g_pos2[CE2];
__device__ int   g_bsum[64];
__device__ int   g_bar[3];

// ---------------------------------------------------------------------------
// device-wide barrier for the persistent CSR kernel (NBG co-resident blocks).
// Barrier k resets counter (k+2)%3 at last-arrival: that barrier was fully
// passed two phases ago (or in the previous launch), so the reset is safe and
// the counters are clean for every graph replay.
// ---------------------------------------------------------------------------
__device__ __forceinline__ void grid_barrier(int k, int nb) {
    __syncthreads();
    __threadfence();
    if (threadIdx.x == 0) {
        int v = atomicAdd(&g_bar[k], 1);
        if (v == nb - 1) g_bar[(k + 2) % 3] = 0;
        while (*(volatile int*)&g_bar[k] < nb) { }
        __threadfence();
    }
    __syncthreads();
}

// ---------------------------------------------------------------------------
// ONE persistent kernel: count+tickets -> segmented scan -> atomic-free fill
// ---------------------------------------------------------------------------
__global__ void __launch_bounds__(1024) k_csr(const int* __restrict__ s1,
                                              const int* __restrict__ d1,
                                              const int* __restrict__ s2,
                                              const int* __restrict__ d2,
                                              int E1, int E2) {
    const int nb = gridDim.x;
    const int gt = blockIdx.x * 1024 + threadIdx.x;
    const int gs = nb * 1024;

    // ---- phase 1: histogram + ticket assignment ----
    for (int i = gt; i < E1; i += gs)
        g_pos1[i] = atomicAdd(g_cnt1 + d1[i], 1);
    for (int j = gt; j < E2; j += gs)
        g_pos2[j] = atomicAdd(g_cnt2 + d2[j], 1);

    grid_barrier(0, nb);

    // ---- phase 2a: block-local exclusive scan (blocks 0..NBT-1) ----
    __shared__ int ps[1024];
    __shared__ int add_s;
    const int b = blockIdx.x;
    int lay = 0, bb = 0, n = 0, segbase = 0;
    int* cnt = nullptr;
    int* off = nullptr;
    int local_ex = 0;
    if (b < NBT) {
        lay = (b >= NB1);
        bb = lay ? b - NB1 : b;
        n = lay ? CN2 : CN1;
        segbase = lay ? NB1 : 0;
        cnt = lay ? g_cnt2 : g_cnt1;
        off = lay ? g_off2 : g_off1;
        int t = threadIdx.x;
        int i = bb * 1024 + t;
        int v = (i < n) ? cnt[i] : 0;
        ps[t] = v;
        __syncthreads();
        #pragma unroll
        for (int d = 1; d < 1024; d <<= 1) {
            int u = (t >= d) ? ps[t - d] : 0;
            __syncthreads();
            ps[t] += u;
            __syncthreads();
        }
        local_ex = ps[t] - v;
        if (t == 1023) g_bsum[b] = ps[1023];
    }

    grid_barrier(1, nb);

    // ---- phase 2b: apply block prefix, reset cnt, set off[n] ----
    if (b < NBT) {
        int t = threadIdx.x;
        if (t == 0) {
            int s = 0;
            for (int j = segbase; j < b; j++) s += g_bsum[j];
            add_s = s;
        }
        __syncthreads();
        int i = bb * 1024 + t;
        if (i < n) { off[i] = local_ex + add_s; cnt[i] = 0; }
        if (i == 0) off[n] = lay ? E2 : E1;
    }

    grid_barrier(2, nb);

    // ---- phase 3: atomic-free fill ----
    for (int i = gt; i < E1; i += gs) {
        int d = d1[i];
        g_csr1[g_off1[d] + g_pos1[i]] = s1[i];
    }
    for (int j = gt; j < E2; j += gs) {
        int d = d2[j];
        g_csr2[g_off2[d] + g_pos2[j]] = s2[j];
    }
}

// ---------------------------------------------------------------------------
// layer-1 gather-mean: warp per dst row, unroll 8
// ---------------------------------------------------------------------------
__global__ void __launch_bounds__(256) k_gather1(const float* __restrict__ x) {
    int w = (blockIdx.x * blockDim.x + threadIdx.x) >> 5;
    if (w >= CN1) return;
    int lane = threadIdx.x & 31;
    int e0 = g_off1[w], e1 = g_off1[w + 1];
    float4 acc = make_float4(0.f, 0.f, 0.f, 0.f);
    int i = e0;
    for (; i + 7 < e1; i += 8) {
        int sid[8];
        #pragma unroll
        for (int j = 0; j < 8; j++) sid[j] = g_csr1[i + j];
        float4 v[8];
        #pragma unroll
        for (int j = 0; j < 8; j++)
            v[j] = ((const float4*)(x + (size_t)sid[j] * CIN))[lane];
        #pragma unroll
        for (int j = 0; j < 8; j++) {
            acc.x += v[j].x; acc.y += v[j].y; acc.z += v[j].z; acc.w += v[j].w;
        }
    }
    for (; i + 3 < e1; i += 4) {
        int s0 = g_csr1[i], s1 = g_csr1[i + 1], s2 = g_csr1[i + 2], s3 = g_csr1[i + 3];
        float4 v0 = ((const float4*)(x + (size_t)s0 * CIN))[lane];
        float4 v1 = ((const float4*)(x + (size_t)s1 * CIN))[lane];
        float4 v2 = ((const float4*)(x + (size_t)s2 * CIN))[lane];
        float4 v3 = ((const float4*)(x + (size_t)s3 * CIN))[lane];
        acc.x += v0.x + v1.x + v2.x + v3.x;
        acc.y += v0.y + v1.y + v2.y + v3.y;
        acc.z += v0.z + v1.z + v2.z + v3.z;
        acc.w += v0.w + v1.w + v2.w + v3.w;
    }
    for (; i < e1; i++) {
        int s = g_csr1[i];
        float4 v = ((const float4*)(x + (size_t)s * CIN))[lane];
        acc.x += v.x; acc.y += v.y; acc.z += v.z; acc.w += v.w;
    }
    float id = 1.0f / fmaxf((float)(e1 - e0), 1.0f);
    acc.x *= id; acc.y *= id; acc.z *= id; acc.w *= id;
    ((float4*)(g_agg1 + (size_t)w * CIN))[lane] = acc;
}

// ---------------------------------------------------------------------------
// tf32 helpers — raw fp32 bits fed to mma.tf32 (HW truncates)
// ---------------------------------------------------------------------------
__device__ __forceinline__ void mma_tf32(float* c, const uint32_t* a, const uint32_t* b) {
    asm volatile(
        "mma.sync.aligned.m16n8k8.row.col.f32.tf32.tf32.f32 "
        "{%0,%1,%2,%3}, {%4,%5,%6,%7}, {%8,%9}, {%0,%1,%2,%3};"
        : "+f"(c[0]), "+f"(c[1]), "+f"(c[2]), "+f"(c[3])
        : "r"(a[0]), "r"(a[1]), "r"(a[2]), "r"(a[3]), "r"(b[0]), "r"(b[1]));
}

__device__ __forceinline__ uint32_t s2u(const void* p) {
    return (uint32_t)__cvta_generic_to_shared(p);
}

__device__ __forceinline__ void cp16(uint32_t dst, const void* src) {
    asm volatile("cp.async.cg.shared.global [%0], [%1], 16;"
                 :: "r"(dst), "l"(src));
}

// ---------------------------------------------------------------------------
// layer-1 GEMM (tf32, 3-stage cp.async pipeline, BM=64 x BN=256)
// ---------------------------------------------------------------------------
#define A_ST 1280
#define B_ST 4224
#define SMEM_GEMM1 ((3 * (A_ST + B_ST)) * 4)

__global__ void __launch_bounds__(256, 2) k_gemm1(const float* __restrict__ x,
                                                  const float* __restrict__ wl,
                                                  const float* __restrict__ wr,
                                                  const float* __restrict__ bias) {
    extern __shared__ float sm[];
    float* Abuf = sm;
    float* Bbuf = sm + 3 * A_ST;

    const int t = threadIdx.x;
    const int lane = t & 31, warp = t >> 5;
    const int warp_m = warp & 1;
    const int warp_n = warp >> 1;
    const int m0 = blockIdx.x * 64;
    const int fr = lane >> 2;
    const int fc = lane & 3;

    const int a_row = t >> 2,  a_kq = (t & 3) * 4;
    const int b_nq  = (t & 63) * 4;

    float acc[2][8][4] = {};

    auto issue = [&](int it, int st) {
        const int kk = (it & 7) * 16;
        const float* Abase = (it < 8) ? g_agg1 : x;
        const float* Bbase = (it < 8) ? wl : wr;
        float* As = Abuf + st * A_ST;
        float* Bs = Bbuf + st * B_ST;
        cp16(s2u(As + a_row * 20 + a_kq),
             Abase + (size_t)(m0 + a_row) * CIN + kk + a_kq);
        #pragma unroll
        for (int i = 0; i < 4; i++) {
            int krow = (t + i * 256) >> 6;
            cp16(s2u(Bs + krow * 264 + b_nq),
                 Bbase + (size_t)(kk + krow) * CHID + b_nq);
        }
    };

    issue(0, 0);
    asm volatile("cp.async.commit_group;");
    issue(1, 1);
    asm volatile("cp.async.commit_group;");

    int st = 0;
    for (int it = 0; it < 16; ++it) {
        asm volatile("cp.async.wait_group 1;");
        __syncthreads();
        if (it + 2 < 16) issue(it + 2, (st + 2) % 3);
        asm volatile("cp.async.commit_group;");

        const uint32_t* A = (const uint32_t*)(Abuf + st * A_ST);
        const uint32_t* B = (const uint32_t*)(Bbuf + st * B_ST);
        #pragma unroll
        for (int ks = 0; ks < 2; ks++) {
            const int kb = ks * 8;
            uint32_t a[2][4], b[8][2];
            #pragma unroll
            for (int mt = 0; mt < 2; mt++) {
                int mr = warp_m * 32 + mt * 16 + fr;
                a[mt][0] = A[mr * 20 + kb + fc];
                a[mt][1] = A[(mr + 8) * 20 + kb + fc];
                a[mt][2] = A[mr * 20 + kb + fc + 4];
                a[mt][3] = A[(mr + 8) * 20 + kb + fc + 4];
            }
            #pragma unroll
            for (int nt = 0; nt < 8; nt++) {
                int nc = warp_n * 64 + nt * 8 + fr;
                b[nt][0] = B[(kb + fc) * 264 + nc];
                b[nt][1] = B[(kb + fc + 4) * 264 + nc];
            }
            #pragma unroll
            for (int mt = 0; mt < 2; mt++)
                #pragma unroll
                for (int nt = 0; nt < 8; nt++)
                    mma_tf32(acc[mt][nt], a[mt], b[nt]);
        }
        st = (st + 1) % 3;
    }

    #pragma unroll
    for (int mt = 0; mt < 2; mt++) {
        int gm = m0 + warp_m * 32 + mt * 16 + fr;
        #pragma unroll
        for (int nt = 0; nt < 8; nt++) {
            int gn = warp_n * 64 + nt * 8 + (fc << 1);
            float b0 = bias[gn], b1 = bias[gn + 1];
            float2 v0 = make_float2(fmaxf(acc[mt][nt][0] + b0, 0.f),
                                    fmaxf(acc[mt][nt][1] + b1, 0.f));
            *(float2*)(g_h + (size_t)gm * CHID + gn) = v0;
            float2 v1 = make_float2(fmaxf(acc[mt][nt][2] + b0, 0.f),
                                    fmaxf(acc[mt][nt][3] + b1, 0.f));
            *(float2*)(g_h + (size_t)(gm + 8) * CHID + gn) = v1;
        }
    }
}

// ---------------------------------------------------------------------------
// FUSED layer-2: gather-mean + GEMM + log_softmax. Warp per dst row.
// Lane owns cols {2*lane, 2*lane+1}: float2 weight/bias/output accesses.
// ---------------------------------------------------------------------------
__global__ void __launch_bounds__(256) k_gemm2(const float* __restrict__ wl,
                                               const float* __restrict__ wr,
                                               const float* __restrict__ bias,
                                               float* __restrict__ out) {
    __shared__ float As[8][512];
    int warp = threadIdx.x >> 5, lane = threadIdx.x & 31;
    int m = blockIdx.x * 8 + warp;
    if (m >= CN2) return;

    {
        int e0 = g_off2[m], e1 = g_off2[m + 1];
        float4 a0 = make_float4(0.f, 0.f, 0.f, 0.f);
        float4 a1 = a0;
        int i = e0;
        for (; i + 1 < e1; i += 2) {
            const float4* p0 = (const float4*)(g_h + (size_t)g_csr2[i] * CHID);
            const float4* p1 = (const float4*)(g_h + (size_t)g_csr2[i + 1] * CHID);
            float4 u0 = p0[lane], u1 = p0[lane + 32];
            float4 v0 = p1[lane], v1 = p1[lane + 32];
            a0.x += u0.x + v0.x; a0.y += u0.y + v0.y;
            a0.z += u0.z + v0.z; a0.w += u0.w + v0.w;
            a1.x += u1.x + v1.x; a1.y += u1.y + v1.y;
            a1.z += u1.z + v1.z; a1.w += u1.w + v1.w;
        }
        for (; i < e1; i++) {
            const float4* p = (const float4*)(g_h + (size_t)g_csr2[i] * CHID);
            float4 u0 = p[lane], u1 = p[lane + 32];
            a0.x += u0.x; a0.y += u0.y; a0.z += u0.z; a0.w += u0.w;
            a1.x += u1.x; a1.y += u1.y; a1.z += u1.z; a1.w += u1.w;
        }
        float id = 1.0f / fmaxf((float)(e1 - e0), 1.0f);
        a0.x *= id; a0.y *= id; a0.z *= id; a0.w *= id;
        a1.x *= id; a1.y *= id; a1.z *= id; a1.w *= id;
        ((float4*)As[warp])[lane] = a0;
        ((float4*)As[warp])[lane + 32] = a1;
    }
    #pragma unroll
    for (int i = 0; i < 8; i++)
        As[warp][CHID + lane + 32 * i] = g_h[(size_t)m * CHID + lane + 32 * i];
    __syncwarp();

    const float2* wlv = (const float2*)wl;
    const float2* wrv = (const float2*)wr;
    float acc0 = 0.f, acc1 = 0.f;
    const float* A = As[warp];
    #pragma unroll 8
    for (int k = 0; k < CHID; k++) {
        float a = A[k];
        float2 w = wlv[k * 32 + lane];
        acc0 += a * w.x;
        acc1 += a * w.y;
    }
    #pragma unroll 8
    for (int k = 0; k < CHID; k++) {
        float a = A[CHID + k];
        float2 w = wrv[k * 32 + lane];
        acc0 += a * w.x;
        acc1 += a * w.y;
    }
    float2 bv = ((const float2*)bias)[lane];
    acc0 += bv.x;
    acc1 += bv.y;

    float mx = fmaxf(acc0, acc1);
    #pragma unroll
    for (int o = 16; o > 0; o >>= 1) mx = fmaxf(mx, __shfl_xor_sync(0xFFFFFFFFu, mx, o));
    float s = expf(acc0 - mx) + expf(acc1 - mx);
    #pragma unroll
    for (int o = 16; o > 0; o >>= 1) s += __shfl_xor_sync(0xFFFFFFFFu, s, o);
    float lse = mx + logf(s);
    ((float2*)(out + (size_t)m * COUT))[lane] = make_float2(acc0 - lse, acc1 - lse);
}

// ---------------------------------------------------------------------------
extern "C" void kernel_launch(void* const* d_in, const int* in_sizes, int n_in,
                              void* d_out, int out_size) {
    const float* x    = (const float*)d_in[0];
    const int*   src1 = (const int*)d_in[1];
    const int*   dst1 = (const int*)d_in[2];
    const int*   src2 = (const int*)d_in[3];
    const int*   dst2 = (const int*)d_in[4];
    const float* wl1  = (const float*)d_in[5];
    const float* bl1  = (const float*)d_in[6];
    const float* wr1  = (const float*)d_in[7];
    const float* wl2  = (const float*)d_in[8];
    const float* bl2  = (const float*)d_in[9];
    const float* wr2  = (const float*)d_in[10];
    int E1 = in_sizes[1];
    int E2 = in_sizes[3];

    cudaFuncSetAttribute(k_gemm1, cudaFuncAttributeMaxDynamicSharedMemorySize,
                         SMEM_GEMM1);

    k_csr<<<NBG, 1024>>>(src1, dst1, src2, dst2, E1, E2);
    k_gather1<<<(CN1 * 32 + 255) / 256, 256>>>(x);
    k_gemm1<<<CN1 / 64, 256, SMEM_GEMM1>>>(x, wl1, wr1, bl1);
    k_gemm2<<<(CN2 + 7) / 8, 256>>>(wl2, wr2, bl2, (float*)d_out);
}